// round 14
// baseline (speedup 1.0000x reference)
#include <cuda_runtime.h>
#include <math.h>

#define WW 1024
#define HH 1024
#define BB 8
#define HWSZ (1024*1024)
#define EPSF 1e-10f
#define NTILES 1024u   /* BB * (HH/8) */

// Global state. Zero-initialized at module load; the last block of each
// launch resets everything after use, so each graph replay sees zeros.
// g_acc layout: lp[3] @0, lpat[3] @3, I[3*8] @6, Up[3*8] @30, T[8] @54
__device__ double   g_acc[62];
__device__ unsigned g_ticket;
__device__ unsigned g_done;

__device__ __forceinline__ double ldcg_d(const double* p) {
    double v;
    asm volatile("ld.global.cg.f64 %0, [%1];" : "=d"(v) : "l"(p));
    return v;
}

// Fused persistent kernel. 304 blocks x 256 threads. Blocks pull tile IDs
// from an atomic ticket (tile = one (b, 8-row band)); each thread owns a
// 4-wide x 8-tall micro-tile. The 7x7 circular conv (29 taps, 1/29) over
// zero-padded target uses per-row horizontal window sums (7/5/5/5/5-wide,
// 1-wide at |dy|=3), 4 pixels byte-packed per u32 (counts <= 29).
// The last block to finish performs the scalar finalize and resets state.
__global__ __launch_bounds__(256, 2)
void combine_loss_fused(const float* __restrict__ pred,
                        const float* __restrict__ diss,
                        const int*   __restrict__ target,
                        const float* __restrict__ diffp,
                        const float* __restrict__ sigmap,
                        float*       __restrict__ out)
{
    const int tid  = threadIdx.x;
    const int c0   = tid << 2;          // leftmost of this thread's 4 columns
    const int lane = tid & 31;
    const int wrp  = tid >> 5;

    __shared__ unsigned s_tile;
    __shared__ float    red[13][8];

    for (;;) {
        if (tid == 0) s_tile = atomicAdd(&g_ticket, 1u);
        __syncthreads();
        const unsigned t = s_tile;
        if (t >= NTILES) break;

        const int b  = (int)(t >> 7);
        const int h0 = (int)(t & 127u) << 3;

        const int* __restrict__ tb = target + (size_t)b * HWSZ;

        unsigned cnt_p[8];   // packed conv counts, byte p = column c0+p
        unsigned ctr_p[8];   // packed center target values
#pragma unroll
        for (int j = 0; j < 8; j++) cnt_p[j] = 0u;

#pragma unroll
        for (int a = 0; a < 14; a++) {
            const int r = h0 - 3 + a;
            int4 A = make_int4(0,0,0,0), B = A, C = A;
            if ((unsigned)r < (unsigned)HH) {
                const int* row = tb + (size_t)r * WW + c0;
                B = *(const int4*)row;                         // c0..c0+3
                if (c0 != 0)      A = *(const int4*)(row - 4); // c0-4..c0-1
                if (c0 != WW - 4) C = *(const int4*)(row + 4); // c0+4..c0+7
            }
            const int t0=A.x, t1=A.y, t2=A.z, t3=A.w;
            const int t4=B.x, t5=B.y, t6=B.z, t7=B.w;
            const int t8=C.x, t9=C.y, t10=C.z;
            const int ps1=t0+t1, ps2=ps1+t2, ps3=ps2+t3, ps4=ps3+t4,
                      ps5=ps4+t5, ps6=ps5+t6, ps7=ps6+t7, ps8=ps7+t8,
                      ps9=ps8+t9, ps10=ps9+t10;
            // pixel p center at t[4+p]; 7-win = t[p+1..p+7]; 5-win = t[p+2..p+6]
            const unsigned s7 = (unsigned)(ps7 - t0)
                              | ((unsigned)(ps8 - ps1) << 8)
                              | ((unsigned)(ps9 - ps2) << 16)
                              | ((unsigned)(ps10 - ps3) << 24);
            const unsigned s5 = (unsigned)(ps6 - ps1)
                              | ((unsigned)(ps7 - ps2) << 8)
                              | ((unsigned)(ps8 - ps3) << 16)
                              | ((unsigned)(ps9 - ps4) << 24);
            const unsigned s1 = (unsigned)t4 | ((unsigned)t5 << 8)
                              | ((unsigned)t6 << 16) | ((unsigned)t7 << 24);

            if (a >= 3 && a <= 10) { cnt_p[a-3] += s7; ctr_p[a-3] = s1; }
            if (a >= 1 && a <= 8)  cnt_p[a-1] += s5;
            if (a >= 2 && a <= 9)  cnt_p[a-2] += s5;
            if (a >= 4 && a <= 11) cnt_p[a-4] += s5;
            if (a >= 5 && a <= 12) cnt_p[a-5] += s5;
            if (a <= 7)            cnt_p[a]   += s1;
            if (a >= 6)            cnt_p[a-6] += s1;
        }

        // acc: 0-2 lp, 3-5 lp*at, 6-8 I, 9-11 sum(p1), 12 sum(t)
        float acc[13];
#pragma unroll
        for (int k = 0; k < 13; k++) acc[k] = 0.f;

        const size_t base = (size_t)h0 * WW + c0;
        const float* __restrict__ p0a = pred + (size_t)(b * 2) * HWSZ + base;
        const float* __restrict__ p0b = p0a + HWSZ;
        const float* __restrict__ p1a = pred + (size_t)((BB + b) * 2) * HWSZ + base;
        const float* __restrict__ p1b = p1a + HWSZ;
        const float* __restrict__ dda = diss + (size_t)(b * 2) * HWSZ + base;
        const float* __restrict__ ddb = dda + HWSZ;

#pragma unroll
        for (int j = 0; j < 8; j++) {
            const size_t off = (size_t)j * WW;
            const float4 a0 = __ldcs((const float4*)(p0a + off));
            const float4 a1 = __ldcs((const float4*)(p0b + off));
            const float4 b0 = __ldcs((const float4*)(p1a + off));
            const float4 b1 = __ldcs((const float4*)(p1b + off));
            const float4 e0 = __ldcs((const float4*)(dda + off));
            const float4 e1 = __ldcs((const float4*)(ddb + off));
            const float A0[4] = {a0.x, a0.y, a0.z, a0.w};
            const float A1[4] = {a1.x, a1.y, a1.z, a1.w};
            const float B0[4] = {b0.x, b0.y, b0.z, b0.w};
            const float B1[4] = {b1.x, b1.y, b1.z, b1.w};
            const float E0[4] = {e0.x, e0.y, e0.z, e0.w};
            const float E1[4] = {e1.x, e1.y, e1.z, e1.w};
            const unsigned cp = cnt_p[j], tp = ctr_p[j];

#pragma unroll
            for (int p = 0; p < 4; p++) {
                const int   ti  = (int)((tp >> (8 * p)) & 255u);
                const int   cnt = (int)((cp >> (8 * p)) & 255u);
                const float tf  = (float)ti;
                // |t - cnt/29| = |29t - cnt| / 29
                const float at  = (float)abs(29 * ti - cnt) * (1.0f / 29.0f);

                // tensor 0: softmax(pred[0]) as sigmoid
                {
                    const float e  = __expf(A0[p] - A1[p]);
                    const float q  = __fdividef(1.0f, 1.0f + e);  // p1
                    const float pt = ti ? q : e * q;              // exact p0
                    const float lp = __logf(pt + EPSF);
                    acc[0] -= lp; acc[3] -= lp * at; acc[6] += q * tf; acc[9] += q;
                }
                // tensor 1: softmax(pred[1])
                {
                    const float e  = __expf(B0[p] - B1[p]);
                    const float q  = __fdividef(1.0f, 1.0f + e);
                    const float pt = ti ? q : e * q;
                    const float lp = __logf(pt + EPSF);
                    acc[1] -= lp; acc[4] -= lp * at; acc[7] += q * tf; acc[10] += q;
                }
                // tensor 2: Diss used directly
                {
                    const float pt = ti ? E1[p] : E0[p];
                    const float lp = __logf(pt + EPSF);
                    acc[2] -= lp; acc[5] -= lp * at; acc[8] += E1[p] * tf; acc[11] += E1[p];
                }
                acc[12] += tf;
            }
        }

        // Per-tile block reduction of 13 values, then FP64 RED atomics.
#pragma unroll
        for (int k = 0; k < 13; k++) {
            float v = acc[k];
#pragma unroll
            for (int o = 16; o > 0; o >>= 1)
                v += __shfl_down_sync(0xFFFFFFFFu, v, o);
            if (lane == 0) red[k][wrp] = v;
        }
        __syncthreads();

        if (tid < 13) {
            const int k = tid;
            double s = 0.0;
#pragma unroll
            for (int q = 0; q < 8; q++) s += (double)red[k][q];
            int idx;
            if (k < 6)        idx = k;                      // lp, lpat
            else if (k < 9)   idx = 6  + (k - 6) * 8 + b;   // I
            else if (k < 12)  idx = 30 + (k - 9) * 8 + b;   // Up
            else              idx = 54 + b;                 // T
            atomicAdd(&g_acc[idx], s);
        }
        // loop top's __syncthreads orders these atomics before red[] reuse
    }

    // ---- completion: last block finalizes and resets state ----
    __threadfence();
    __shared__ unsigned s_rank;
    if (tid == 0) s_rank = atomicAdd(&g_done, 1u);
    __syncthreads();
    if (s_rank != gridDim.x - 1) return;

    __shared__ double v[62];
    __shared__ double inv_s[3];
    __shared__ double dice_sum;

    if (tid < 62) v[tid] = ldcg_d(&g_acc[tid]);
    if (tid < 3) {
        const double s = (double)sigmap[tid] * (double)sigmap[tid];
        inv_s[tid] = 1.0 / s;   // 3 parallel FP64 divides
    }
    __syncthreads();

    // reset for the next graph replay
    if (tid < 62) g_acc[tid] = 0.0;
    if (tid == 0) { g_ticket = 0u; g_done = 0u; }

    // dice: 24 independent FP64 divides in warp 0, shuffle-reduced
    if (tid < 32) {
        double d = 0.0;
        if (tid < 24) {
            const int k = tid >> 3, bb = tid & 7;
            const double U = v[30 + k * 8 + bb] + v[54 + bb] + 1e-10;
            d = 2.0 * v[6 + k * 8 + bb] / U;
        }
#pragma unroll
        for (int o = 16; o > 0; o >>= 1)
            d += __shfl_down_sync(0xFFFFFFFFu, d, o);
        if (tid == 0) dice_sum = d;
    }
    __syncthreads();

    if (tid == 0) {
        const double invBHW = 1.0 / ((double)BB * (double)HWSZ);
        double loss = 0.0;
        loss += (v[0] + v[1] + v[2]) * invBHW * inv_s[0];            // focal
        loss += (v[3] + v[4] + v[5]) * invBHW * inv_s[2];            // edge
        loss += (3.0 - dice_sum * (1.0 / (double)BB)) * inv_s[1];    // dice
        loss += (double)diffp[0];
        loss -= 0.5 * (log(inv_s[0]) + log(inv_s[1]) + log(inv_s[2]));
        out[0] = (float)loss;
    }
}

extern "C" void kernel_launch(void* const* d_in, const int* in_sizes, int n_in,
                              void* d_out, int out_size)
{
    const float* pred   = (const float*)d_in[0];  // (2, 8, 2, 1024, 1024)
    const float* diss   = (const float*)d_in[1];  // (1, 8, 2, 1024, 1024)
    const int*   target = (const int*)  d_in[2];  // (8, 1024, 1024)
    const float* diffp  = (const float*)d_in[3];  // scalar
    const float* sigmap = (const float*)d_in[4];  // (3,)
    float* out = (float*)d_out;

    // 304 persistent blocks (2 CTAs/SM on 152 SMs), work via atomic ticket.
    combine_loss_fused<<<304, 256>>>(pred, diss, target, diffp, sigmap, out);
}

// round 15
// speedup vs baseline: 1.1156x; 1.1156x over previous
#include <cuda_runtime.h>
#include <math.h>

#define WW 1024
#define HH 1024
#define BB 8
#define HWSZ (1024*1024)
#define EPSF 1e-10f
#define NBLOCKS 2048u   /* BB * (HH/4) */

// Global state. Zero-initialized at module load; the last block of each
// launch resets everything after use, so each graph replay sees zeros.
// g_acc layout: lp[3] @0, lpat[3] @3, I[3*8] @6, Up[3*8] @30, T[8] @54
__device__ double   g_acc[62];
__device__ unsigned g_done;

__device__ __forceinline__ double ldcg_d(const double* p) {
    double v;
    asm volatile("ld.global.cg.f64 %0, [%1];" : "=d"(v) : "l"(p));
    return v;
}

// Static-grid fused kernel. Grid (1, HH/4, BB), 256 threads. Each thread
// owns a 4-wide (float4/int4 aligned) x 4-tall micro-tile. The 7x7 circular
// conv (29 taps, weight 1/29) over zero-padded target is built from per-row
// horizontal window sums (7-wide center, 5-wide at |dy|=1,2, 1-wide at
// |dy|=3), with 4 pixels byte-packed per u32 (counts <= 29 fit a byte).
// The last block to finish performs the scalar finalize and resets state.
__global__ __launch_bounds__(256, 3)
void combine_loss_fused(const float* __restrict__ pred,
                        const float* __restrict__ diss,
                        const int*   __restrict__ target,
                        const float* __restrict__ diffp,
                        const float* __restrict__ sigmap,
                        float*       __restrict__ out)
{
    const int tid  = threadIdx.x;
    const int c0   = tid << 2;          // leftmost of this thread's 4 columns
    const int lane = tid & 31;
    const int wrp  = tid >> 5;
    const int b    = blockIdx.z;
    const int h0   = blockIdx.y << 2;   // top row of this thread's 4 rows

    const int* __restrict__ tb = target + (size_t)b * HWSZ;

    unsigned cnt_p[4];   // packed conv counts, byte p = column c0+p
    unsigned ctr_p[4];   // packed center target values
#pragma unroll
    for (int j = 0; j < 4; j++) cnt_p[j] = 0u;

    // rows r = h0-3 .. h0+6  (a = r - (h0-3), a = 0..9)
#pragma unroll
    for (int a = 0; a < 10; a++) {
        const int r = h0 - 3 + a;
        int4 A = make_int4(0,0,0,0), B = A, C = A;
        if ((unsigned)r < (unsigned)HH) {
            const int* row = tb + (size_t)r * WW + c0;
            B = *(const int4*)row;                         // c0..c0+3
            if (c0 != 0)      A = *(const int4*)(row - 4); // c0-4..c0-1
            if (c0 != WW - 4) C = *(const int4*)(row + 4); // c0+4..c0+7
        }
        const int t0=A.x, t1=A.y, t2=A.z, t3=A.w;
        const int t4=B.x, t5=B.y, t6=B.z, t7=B.w;
        const int t8=C.x, t9=C.y, t10=C.z;
        const int ps1=t0+t1, ps2=ps1+t2, ps3=ps2+t3, ps4=ps3+t4,
                  ps5=ps4+t5, ps6=ps5+t6, ps7=ps6+t7, ps8=ps7+t8,
                  ps9=ps8+t9, ps10=ps9+t10;
        // pixel p center at t[4+p]; 7-win = t[p+1..p+7]; 5-win = t[p+2..p+6]
        const unsigned s7 = (unsigned)(ps7 - t0)
                          | ((unsigned)(ps8 - ps1) << 8)
                          | ((unsigned)(ps9 - ps2) << 16)
                          | ((unsigned)(ps10 - ps3) << 24);
        const unsigned s5 = (unsigned)(ps6 - ps1)
                          | ((unsigned)(ps7 - ps2) << 8)
                          | ((unsigned)(ps8 - ps3) << 16)
                          | ((unsigned)(ps9 - ps4) << 24);
        const unsigned s1 = (unsigned)t4 | ((unsigned)t5 << 8)
                          | ((unsigned)t6 << 16) | ((unsigned)t7 << 24);

        // row a contributes to output j: dy=0 -> s7 @ j=a-3;
        // |dy|=1,2 -> s5 @ j=a-1,a-2,a-4,a-5; |dy|=3 -> s1 @ j=a, a-6
        if (a >= 3 && a <= 6) { cnt_p[a-3] += s7; ctr_p[a-3] = s1; }
        if (a >= 1 && a <= 4) cnt_p[a-1] += s5;
        if (a >= 2 && a <= 5) cnt_p[a-2] += s5;
        if (a >= 4 && a <= 7) cnt_p[a-4] += s5;
        if (a >= 5 && a <= 8) cnt_p[a-5] += s5;
        if (a <= 3)           cnt_p[a]   += s1;
        if (a >= 6)           cnt_p[a-6] += s1;
    }

    // acc: 0-2 lp, 3-5 lp*at, 6-8 I, 9-11 sum(p1), 12 sum(t)
    float acc[13];
#pragma unroll
    for (int k = 0; k < 13; k++) acc[k] = 0.f;

    const size_t base = (size_t)h0 * WW + c0;
    const float* __restrict__ p0a = pred + (size_t)(b * 2) * HWSZ + base;
    const float* __restrict__ p0b = p0a + HWSZ;
    const float* __restrict__ p1a = pred + (size_t)((BB + b) * 2) * HWSZ + base;
    const float* __restrict__ p1b = p1a + HWSZ;
    const float* __restrict__ dda = diss + (size_t)(b * 2) * HWSZ + base;
    const float* __restrict__ ddb = dda + HWSZ;

#pragma unroll
    for (int j = 0; j < 4; j++) {
        const size_t off = (size_t)j * WW;
        const float4 a0 = __ldcs((const float4*)(p0a + off));
        const float4 a1 = __ldcs((const float4*)(p0b + off));
        const float4 b0 = __ldcs((const float4*)(p1a + off));
        const float4 b1 = __ldcs((const float4*)(p1b + off));
        const float4 e0 = __ldcs((const float4*)(dda + off));
        const float4 e1 = __ldcs((const float4*)(ddb + off));
        const float A0[4] = {a0.x, a0.y, a0.z, a0.w};
        const float A1[4] = {a1.x, a1.y, a1.z, a1.w};
        const float B0[4] = {b0.x, b0.y, b0.z, b0.w};
        const float B1[4] = {b1.x, b1.y, b1.z, b1.w};
        const float E0[4] = {e0.x, e0.y, e0.z, e0.w};
        const float E1[4] = {e1.x, e1.y, e1.z, e1.w};
        const unsigned cp = cnt_p[j], tp = ctr_p[j];

#pragma unroll
        for (int p = 0; p < 4; p++) {
            const int   ti  = (int)((tp >> (8 * p)) & 255u);
            const int   cnt = (int)((cp >> (8 * p)) & 255u);
            const float tf  = (float)ti;
            // |t - cnt/29| = |29t - cnt| / 29
            const float at  = (float)abs(29 * ti - cnt) * (1.0f / 29.0f);

            // tensor 0: softmax(pred[0]) as sigmoid
            {
                const float e  = __expf(A0[p] - A1[p]);
                const float q  = __fdividef(1.0f, 1.0f + e);  // p1
                const float pt = ti ? q : e * q;              // exact p0
                const float lp = __logf(pt + EPSF);
                acc[0] -= lp; acc[3] -= lp * at; acc[6] += q * tf; acc[9] += q;
            }
            // tensor 1: softmax(pred[1])
            {
                const float e  = __expf(B0[p] - B1[p]);
                const float q  = __fdividef(1.0f, 1.0f + e);
                const float pt = ti ? q : e * q;
                const float lp = __logf(pt + EPSF);
                acc[1] -= lp; acc[4] -= lp * at; acc[7] += q * tf; acc[10] += q;
            }
            // tensor 2: Diss used directly
            {
                const float pt = ti ? E1[p] : E0[p];
                const float lp = __logf(pt + EPSF);
                acc[2] -= lp; acc[5] -= lp * at; acc[8] += E1[p] * tf; acc[11] += E1[p];
            }
            acc[12] += tf;
        }
    }

    // Block reduction of 13 values, then FP64 atomics (62 addresses total).
    __shared__ float red[13][8];
#pragma unroll
    for (int k = 0; k < 13; k++) {
        float v = acc[k];
#pragma unroll
        for (int o = 16; o > 0; o >>= 1)
            v += __shfl_down_sync(0xFFFFFFFFu, v, o);
        if (lane == 0) red[k][wrp] = v;
    }
    __syncthreads();

    if (tid < 13) {
        const int k = tid;
        double s = 0.0;
#pragma unroll
        for (int q = 0; q < 8; q++) s += (double)red[k][q];
        int idx;
        if (k < 6)        idx = k;                      // lp, lpat
        else if (k < 9)   idx = 6  + (k - 6) * 8 + b;   // I
        else if (k < 12)  idx = 30 + (k - 9) * 8 + b;   // Up
        else              idx = 54 + b;                 // T
        atomicAdd(&g_acc[idx], s);
    }

    // ---- completion: last block finalizes and resets state ----
    __threadfence();
    __shared__ unsigned s_rank;
    if (tid == 0) s_rank = atomicAdd(&g_done, 1u);
    __syncthreads();
    if (s_rank != NBLOCKS - 1u) return;

    __shared__ double v[62];
    __shared__ double inv_s[3];
    __shared__ double dice_sum;

    if (tid < 62) v[tid] = ldcg_d(&g_acc[tid]);
    if (tid < 3) {
        const double s = (double)sigmap[tid] * (double)sigmap[tid];
        inv_s[tid] = 1.0 / s;   // 3 parallel FP64 divides
    }
    __syncthreads();

    // reset for the next graph replay
    if (tid < 62) g_acc[tid] = 0.0;
    if (tid == 0) g_done = 0u;

    // dice: 24 independent FP64 divides in warp 0, shuffle-reduced
    if (tid < 32) {
        double d = 0.0;
        if (tid < 24) {
            const int k = tid >> 3, bb = tid & 7;
            const double U = v[30 + k * 8 + bb] + v[54 + bb] + 1e-10;
            d = 2.0 * v[6 + k * 8 + bb] / U;
        }
#pragma unroll
        for (int o = 16; o > 0; o >>= 1)
            d += __shfl_down_sync(0xFFFFFFFFu, d, o);
        if (tid == 0) dice_sum = d;
    }
    __syncthreads();

    if (tid == 0) {
        const double invBHW = 1.0 / ((double)BB * (double)HWSZ);
        double loss = 0.0;
        loss += (v[0] + v[1] + v[2]) * invBHW * inv_s[0];            // focal
        loss += (v[3] + v[4] + v[5]) * invBHW * inv_s[2];            // edge
        loss += (3.0 - dice_sum * (1.0 / (double)BB)) * inv_s[1];    // dice
        loss += (double)diffp[0];
        loss -= 0.5 * (log(inv_s[0]) + log(inv_s[1]) + log(inv_s[2]));
        out[0] = (float)loss;
    }
}

extern "C" void kernel_launch(void* const* d_in, const int* in_sizes, int n_in,
                              void* d_out, int out_size)
{
    const float* pred   = (const float*)d_in[0];  // (2, 8, 2, 1024, 1024)
    const float* diss   = (const float*)d_in[1];  // (1, 8, 2, 1024, 1024)
    const int*   target = (const int*)  d_in[2];  // (8, 1024, 1024)
    const float* diffp  = (const float*)d_in[3];  // scalar
    const float* sigmap = (const float*)d_in[4];  // (3,)
    float* out = (float*)d_out;

    dim3 grid(1, HH / 4, BB);   // 2048 blocks
    combine_loss_fused<<<grid, 256>>>(pred, diss, target, diffp, sigmap, out);
}

// round 16
// speedup vs baseline: 1.2272x; 1.1000x over previous
#include <cuda_runtime.h>
#include <math.h>

#define WW 1024
#define HH 1024
#define BB 8
#define HWSZ (1024*1024)
#define EPSF 1e-10f
#define NBLOCKS 2048u   /* BB * (HH/4) */

// Global state. Zero-initialized at module load; the last block of each
// launch resets everything after use, so each graph replay sees zeros.
// g_acc layout: lp[3] @0, lpat[3] @3, I[3*8] @6, Up[3*8] @30, T[8] @54
__device__ double   g_acc[62];
__device__ unsigned g_done;

__device__ __forceinline__ double ldcg_d(const double* p) {
    double v;
    asm volatile("ld.global.cg.f64 %0, [%1];" : "=d"(v) : "l"(p));
    return v;
}

// Static-grid fused kernel. Grid (1, HH/4, BB), 256 threads, 4 CTAs/SM.
// Each thread owns a 4-wide (float4/int4 aligned) x 4-tall micro-tile.
// The 7x7 circular conv (29 taps, weight 1/29) over zero-padded target is
// built from per-row horizontal window sums (7-wide center, 5-wide at
// |dy|=1,2, 1-wide at |dy|=3); conv counts byte-packed 4 px/u32, center
// target values bit-packed 16 px/u32. All inner-loop loads use a single
// base register + compile-time immediate offsets (plane stride 4MB fits
// the LDG immediate field).
// The last block to finish performs the scalar finalize and resets state.
__global__ __launch_bounds__(256, 4)
void combine_loss_fused(const float* __restrict__ pred,
                        const float* __restrict__ diss,
                        const int*   __restrict__ target,
                        const float* __restrict__ diffp,
                        const float* __restrict__ sigmap,
                        float*       __restrict__ out)
{
    const int tid  = threadIdx.x;
    const int c0   = tid << 2;          // leftmost of this thread's 4 columns
    const int lane = tid & 31;
    const int wrp  = tid >> 5;
    const int b    = blockIdx.z;
    const int h0   = blockIdx.y << 2;   // top row of this thread's 4 rows

    // Stencil base: row h0-3, column c0. May point out of bounds for edge
    // bands; every dereference below is predicated by the row check.
    const int* __restrict__ tbase =
        target + (size_t)b * HWSZ + (size_t)(h0 - 3) * WW + c0;
    const bool cok_lo = (c0 != 0);
    const bool cok_hi = (c0 != WW - 4);

    unsigned cnt_p[4];   // packed conv counts, byte p = column c0+p
    unsigned ctr_bits = 0u;  // center target bits, bit (j*4+p)
#pragma unroll
    for (int j = 0; j < 4; j++) cnt_p[j] = 0u;

    // rows r = h0-3 .. h0+6  (a = 0..9), offsets a*WW are immediates
#pragma unroll
    for (int a = 0; a < 10; a++) {
        const int r = h0 - 3 + a;
        int4 A = make_int4(0,0,0,0), B = A, C = A;
        if ((unsigned)r < (unsigned)HH) {
            B = *(const int4*)(tbase + a * WW);                  // c0..c0+3
            if (cok_lo) A = *(const int4*)(tbase + a * WW - 4);  // c0-4..c0-1
            if (cok_hi) C = *(const int4*)(tbase + a * WW + 4);  // c0+4..c0+7
        }
        const int t0=A.x, t1=A.y, t2=A.z, t3=A.w;
        const int t4=B.x, t5=B.y, t6=B.z, t7=B.w;
        const int t8=C.x, t9=C.y, t10=C.z;
        const int ps1=t0+t1, ps2=ps1+t2, ps3=ps2+t3, ps4=ps3+t4,
                  ps5=ps4+t5, ps6=ps5+t6, ps7=ps6+t7, ps8=ps7+t8,
                  ps9=ps8+t9, ps10=ps9+t10;
        // pixel p center at t[4+p]; 7-win = t[p+1..p+7]; 5-win = t[p+2..p+6]
        const unsigned s7 = (unsigned)(ps7 - t0)
                          | ((unsigned)(ps8 - ps1) << 8)
                          | ((unsigned)(ps9 - ps2) << 16)
                          | ((unsigned)(ps10 - ps3) << 24);
        const unsigned s5 = (unsigned)(ps6 - ps1)
                          | ((unsigned)(ps7 - ps2) << 8)
                          | ((unsigned)(ps8 - ps3) << 16)
                          | ((unsigned)(ps9 - ps4) << 24);
        const unsigned s1 = (unsigned)t4 | ((unsigned)t5 << 8)
                          | ((unsigned)t6 << 16) | ((unsigned)t7 << 24);

        // row a contributes to output j: dy=0 -> s7 @ j=a-3;
        // |dy|=1,2 -> s5 @ j=a-1,a-2,a-4,a-5; |dy|=3 -> s1 @ j=a, a-6
        if (a >= 3 && a <= 6) {
            cnt_p[a-3] += s7;
            ctr_bits |= (unsigned)(t4 | (t5<<1) | (t6<<2) | (t7<<3)) << ((a-3)*4);
        }
        if (a >= 1 && a <= 4) cnt_p[a-1] += s5;
        if (a >= 2 && a <= 5) cnt_p[a-2] += s5;
        if (a >= 4 && a <= 7) cnt_p[a-4] += s5;
        if (a >= 5 && a <= 8) cnt_p[a-5] += s5;
        if (a <= 3)           cnt_p[a]   += s1;
        if (a >= 6)           cnt_p[a-6] += s1;
    }

    // acc: 0-2 lp, 3-5 lp*at, 6-8 I, 9-11 sum(p1), 12 sum(t)
    float acc[13];
#pragma unroll
    for (int k = 0; k < 13; k++) acc[k] = 0.f;

    // Three live base pointers; partner plane at +HWSZ (4MB immediate),
    // row offsets j*WW immediates.
    const size_t base = (size_t)h0 * WW + c0;
    const float* __restrict__ p0 = pred + (size_t)(b * 2) * HWSZ + base;
    const float* __restrict__ p1 = p0 + (size_t)(BB * 2) * HWSZ;  // +64MB
    const float* __restrict__ dd = diss + (size_t)(b * 2) * HWSZ + base;

#pragma unroll
    for (int j = 0; j < 4; j++) {
        const int off = j * WW;
        const float4 a0 = __ldcs((const float4*)(p0 + off));
        const float4 a1 = __ldcs((const float4*)(p0 + off + HWSZ));
        const float4 b0 = __ldcs((const float4*)(p1 + off));
        const float4 b1 = __ldcs((const float4*)(p1 + off + HWSZ));
        const float4 e0 = __ldcs((const float4*)(dd + off));
        const float4 e1 = __ldcs((const float4*)(dd + off + HWSZ));
        const float A0[4] = {a0.x, a0.y, a0.z, a0.w};
        const float A1[4] = {a1.x, a1.y, a1.z, a1.w};
        const float B0[4] = {b0.x, b0.y, b0.z, b0.w};
        const float B1[4] = {b1.x, b1.y, b1.z, b1.w};
        const float E0[4] = {e0.x, e0.y, e0.z, e0.w};
        const float E1[4] = {e1.x, e1.y, e1.z, e1.w};
        const unsigned cp  = cnt_p[j];
        const unsigned tb4 = (ctr_bits >> (j * 4)) & 0xFu;

#pragma unroll
        for (int p = 0; p < 4; p++) {
            const int   ti  = (int)((tb4 >> p) & 1u);
            const int   cnt = (int)((cp >> (8 * p)) & 255u);
            const float tf  = (float)ti;
            // |t - cnt/29| = |29t - cnt| / 29
            const float at  = (float)abs(29 * ti - cnt) * (1.0f / 29.0f);

            // tensor 0: softmax(pred[0]) as sigmoid
            {
                const float e  = __expf(A0[p] - A1[p]);
                const float q  = __fdividef(1.0f, 1.0f + e);  // p1
                const float pt = ti ? q : e * q;              // exact p0
                const float lp = __logf(pt + EPSF);
                acc[0] -= lp; acc[3] -= lp * at; acc[6] += q * tf; acc[9] += q;
            }
            // tensor 1: softmax(pred[1])
            {
                const float e  = __expf(B0[p] - B1[p]);
                const float q  = __fdividef(1.0f, 1.0f + e);
                const float pt = ti ? q : e * q;
                const float lp = __logf(pt + EPSF);
                acc[1] -= lp; acc[4] -= lp * at; acc[7] += q * tf; acc[10] += q;
            }
            // tensor 2: Diss used directly
            {
                const float pt = ti ? E1[p] : E0[p];
                const float lp = __logf(pt + EPSF);
                acc[2] -= lp; acc[5] -= lp * at; acc[8] += E1[p] * tf; acc[11] += E1[p];
            }
            acc[12] += tf;
        }
    }

    // Block reduction of 13 values, then FP64 atomics (62 addresses total).
    __shared__ float red[13][8];
#pragma unroll
    for (int k = 0; k < 13; k++) {
        float v = acc[k];
#pragma unroll
        for (int o = 16; o > 0; o >>= 1)
            v += __shfl_down_sync(0xFFFFFFFFu, v, o);
        if (lane == 0) red[k][wrp] = v;
    }
    __syncthreads();

    if (tid < 13) {
        const int k = tid;
        double s = 0.0;
#pragma unroll
        for (int q = 0; q < 8; q++) s += (double)red[k][q];
        int idx;
        if (k < 6)        idx = k;                      // lp, lpat
        else if (k < 9)   idx = 6  + (k - 6) * 8 + b;   // I
        else if (k < 12)  idx = 30 + (k - 9) * 8 + b;   // Up
        else              idx = 54 + b;                 // T
        atomicAdd(&g_acc[idx], s);
    }

    // ---- completion: last block finalizes and resets state ----
    __threadfence();
    __shared__ unsigned s_rank;
    if (tid == 0) s_rank = atomicAdd(&g_done, 1u);
    __syncthreads();
    if (s_rank != NBLOCKS - 1u) return;

    __shared__ double v[62];
    __shared__ double inv_s[3];
    __shared__ double dice_sum;

    if (tid < 62) v[tid] = ldcg_d(&g_acc[tid]);
    if (tid < 3) {
        const double s = (double)sigmap[tid] * (double)sigmap[tid];
        inv_s[tid] = 1.0 / s;   // 3 parallel FP64 divides
    }
    __syncthreads();

    // reset for the next graph replay
    if (tid < 62) g_acc[tid] = 0.0;
    if (tid == 0) g_done = 0u;

    // dice: 24 independent FP64 divides in warp 0, shuffle-reduced
    if (tid < 32) {
        double d = 0.0;
        if (tid < 24) {
            const int k = tid >> 3, bb = tid & 7;
            const double U = v[30 + k * 8 + bb] + v[54 + bb] + 1e-10;
            d = 2.0 * v[6 + k * 8 + bb] / U;
        }
#pragma unroll
        for (int o = 16; o > 0; o >>= 1)
            d += __shfl_down_sync(0xFFFFFFFFu, d, o);
        if (tid == 0) dice_sum = d;
    }
    __syncthreads();

    if (tid == 0) {
        const double invBHW = 1.0 / ((double)BB * (double)HWSZ);
        double loss = 0.0;
        loss += (v[0] + v[1] + v[2]) * invBHW * inv_s[0];            // focal
        loss += (v[3] + v[4] + v[5]) * invBHW * inv_s[2];            // edge
        loss += (3.0 - dice_sum * (1.0 / (double)BB)) * inv_s[1];    // dice
        loss += (double)diffp[0];
        loss -= 0.5 * (log(inv_s[0]) + log(inv_s[1]) + log(inv_s[2]));
        out[0] = (float)loss;
    }
}

extern "C" void kernel_launch(void* const* d_in, const int* in_sizes, int n_in,
                              void* d_out, int out_size)
{
    const float* pred   = (const float*)d_in[0];  // (2, 8, 2, 1024, 1024)
    const float* diss   = (const float*)d_in[1];  // (1, 8, 2, 1024, 1024)
    const int*   target = (const int*)  d_in[2];  // (8, 1024, 1024)
    const float* diffp  = (const float*)d_in[3];  // scalar
    const float* sigmap = (const float*)d_in[4];  // (3,)
    float* out = (float*)d_out;

    dim3 grid(1, HH / 4, BB);   // 2048 blocks
    combine_loss_fused<<<grid, 256>>>(pred, diss, target, diffp, sigmap, out);
}